// round 10
// baseline (speedup 1.0000x reference)
#include <cuda_runtime.h>
#include <cuda_bf16.h>
#include <cstdint>

#define N_NODES 100000
#define N_EDGES 640000
#define FEAT 128
#define HID 256
#define NCLS 10

// ---------------------------------------------------------------------------
// Persistent scratch (re-initialized every launch before use).
// ---------------------------------------------------------------------------
__device__ __align__(16) float g_agg1[N_NODES * FEAT];
__device__ __align__(16) float g_h1[N_NODES * HID];
__device__ __align__(16) float g_h[N_NODES * HID];
__device__ __align__(16) float g_agg2[N_NODES * HID];
__device__ __align__(16) float g_z[N_NODES * HID];
__device__ int g_src[N_EDGES];
__device__ int g_dst[N_EDGES];
__device__ int g_ssrc[N_EDGES];
__device__ int g_cnt[N_NODES];
__device__ int g_off[N_NODES + 1];
__device__ int g_cur[N_NODES];
__device__ int g_bsum[128];
// row scales (A-side) and col scales (B-side)
__device__ float g_sa1[N_NODES];   // rows of agg1
__device__ float g_sh1[N_NODES];   // rows of h1 (gemm1 epilogue atomicMax)
__device__ float g_sa2[N_NODES];   // rows of agg2
__device__ float g_sb[3 * 256];    // col absmax of W1a|W1b|W2a
// quantized weights, fragment-order: [chunk][plane][group(32)][lane(32)][reg(2)]
__device__ __align__(16) uint32_t g_wq1[4 * 4096];   // W1a K=128
__device__ __align__(16) uint32_t g_wq2[8 * 4096];   // W1b K=256
__device__ __align__(16) uint32_t g_wq3[8 * 4096];   // W2a K=256

// ---------------------------------------------------------------------------
// PTX helpers
// ---------------------------------------------------------------------------
#define LDSM4(r, a)                                                           \
    asm volatile("ldmatrix.sync.aligned.m8n8.x4.shared.b16 {%0,%1,%2,%3}, [%4];" \
                 : "=r"((r)[0]), "=r"((r)[1]), "=r"((r)[2]), "=r"((r)[3])     \
                 : "r"(a))
#define IMMA16832(c, A, B)                                                    \
    asm volatile(                                                             \
        "mma.sync.aligned.m16n8k32.row.col.s32.s8.s8.s32 "                    \
        "{%0,%1,%2,%3},{%4,%5,%6,%7},{%8,%9},{%0,%1,%2,%3};"                  \
        : "+r"((c)[0]), "+r"((c)[1]), "+r"((c)[2]), "+r"((c)[3])              \
        : "r"((A)[0]), "r"((A)[1]), "r"((A)[2]), "r"((A)[3]), "r"((B)[0]),    \
          "r"((B)[1]))
#define CP_ASYNC16(dst, src)                                                  \
    asm volatile("cp.async.cg.shared.global [%0], [%1], 16;" ::"r"(dst),      \
                 "l"(src) : "memory")
#define CP_COMMIT() asm volatile("cp.async.commit_group;" ::: "memory")
#define CP_WAIT0() asm volatile("cp.async.wait_group 0;" ::: "memory")

__device__ __forceinline__ uint32_t smem_u32(const void* p) {
    uint32_t a;
    asm("{ .reg .u64 t; cvta.to.shared.u64 t, %1; cvt.u32.u64 %0, t; }"
        : "=r"(a) : "l"(p));
    return a;
}
// quantize u in [-127,127] to (q1, q2) with u ~= q1 + q2/254
__device__ __forceinline__ void qpair(float u, int& q1, int& q2) {
    float q1f = rintf(u);
    q1 = (int)q1f;
    q1 = max(-127, min(127, q1));
    q2 = (int)rintf((u - q1f) * 254.f);
    q2 = max(-127, min(127, q2));
}
__device__ __forceinline__ float ld_sa(const float* p, int i) {
    return fmaxf(p[i], 1e-20f);
}

// ---------------------------------------------------------------------------
// Setup 1: col absmax of weights (blocks 0-2) + zero bins/scales (blocks 3+)
// ---------------------------------------------------------------------------
__global__ void setup_colmax_kernel(const float* __restrict__ W1a,
                                    const float* __restrict__ W1b,
                                    const float* __restrict__ W2a) {
    int b = blockIdx.x;
    int t = threadIdx.x;
    if (b < 3) {
        const float* W = (b == 0) ? W1a : (b == 1) ? W1b : W2a;
        int K = (b == 0) ? 128 : 256;
        float m = 0.f;
        for (int k = 0; k < K; k++) m = fmaxf(m, fabsf(W[k * 256 + t]));
        g_sb[b * 256 + t] = fmaxf(m, 1e-20f);
    } else {
        int i = (b - 3) * 256 + t;
        if (i < N_NODES) {
            g_cnt[i] = 0;
            g_sh1[i] = 0.f;
        }
    }
}

// ---------------------------------------------------------------------------
// Setup 2: quantize weights into IMMA B-fragment order.
// word i: chunk=i>>12; plane=(i>>11)&1; group=(i>>6)&31; lane=(i>>1)&31; reg=i&1
// byte j: k = chunk*32 + (lane&3)*4 + reg*16 + j; n = group*8 + lane/4
// ---------------------------------------------------------------------------
__device__ __forceinline__ void quant_w(const float* __restrict__ W,
                                        const float* __restrict__ sb,
                                        uint32_t* __restrict__ out, int i) {
    int chunk = i >> 12;
    int plane = (i >> 11) & 1;
    int group = (i >> 6) & 31;
    int lane = (i >> 1) & 31;
    int reg = i & 1;
    int n = group * 8 + (lane >> 2);
    float inv = 127.f / sb[n];
    uint32_t w = 0;
#pragma unroll
    for (int j = 0; j < 4; j++) {
        int k = chunk * 32 + (lane & 3) * 4 + reg * 16 + j;
        int q1, q2;
        qpair(W[(size_t)k * 256 + n] * inv, q1, q2);
        int q = plane ? q2 : q1;
        w |= (uint32_t)(q & 0xff) << (8 * j);
    }
    out[i] = w;
}

__global__ void setup_quant_kernel(const float* __restrict__ W1a,
                                   const float* __restrict__ W1b,
                                   const float* __restrict__ W2a) {
    int i = blockIdx.x * 256 + threadIdx.x;
    if (i < 4 * 4096) quant_w(W1a, g_sb, g_wq1, i);
    if (i < 8 * 4096) {
        quant_w(W1b, g_sb + 256, g_wq2, i);
        quant_w(W2a, g_sb + 512, g_wq3, i);
    }
}

// ---------------------------------------------------------------------------
// Edge-index conversion + histogram with per-block dtype sniff.
// ---------------------------------------------------------------------------
__global__ void convert_hist_kernel(const void* __restrict__ ei) {
    __shared__ int s_is64;
    if (threadIdx.x == 0) {
        const unsigned int* w = (const unsigned int*)ei;
        int is64 = 1;
        for (int i = 0; i < 256; i++)
            if (w[2 * i + 1] != 0u) { is64 = 0; break; }
        s_is64 = is64;
    }
    __syncthreads();
    int e = blockIdx.x * 256 + threadIdx.x;
    if (e >= N_EDGES) return;
    int s, d;
    if (s_is64) {
        const long long* p = (const long long*)ei;
        s = (int)p[e];
        d = (int)p[N_EDGES + e];
    } else {
        const int* p = (const int*)ei;
        s = p[e];
        d = p[N_EDGES + e];
    }
    s = min(max(s, 0), N_NODES - 1);
    d = min(max(d, 0), N_NODES - 1);
    g_src[e] = s;
    g_dst[e] = d;
    atomicAdd(&g_cnt[d], 1);
}

__global__ void scan1_kernel() {
    __shared__ int sh[1024];
    const int tid = threadIdx.x;
    int i = blockIdx.x * 1024 + tid;
    int v = (i < N_NODES) ? g_cnt[i] : 0;
    sh[tid] = v;
    __syncthreads();
#pragma unroll
    for (int o = 1; o < 1024; o <<= 1) {
        int t = (tid >= o) ? sh[tid - o] : 0;
        __syncthreads();
        sh[tid] += t;
        __syncthreads();
    }
    if (i < N_NODES) g_off[i] = sh[tid] - v;
    if (tid == 1023) g_bsum[blockIdx.x] = sh[1023];
}

__global__ void scan2_kernel(int nb) {
    __shared__ int sh[128];
    const int tid = threadIdx.x;
    int v = (tid < nb) ? g_bsum[tid] : 0;
    sh[tid] = v;
    __syncthreads();
#pragma unroll
    for (int o = 1; o < 128; o <<= 1) {
        int t = (tid >= o) ? sh[tid - o] : 0;
        __syncthreads();
        sh[tid] += t;
        __syncthreads();
    }
    if (tid < nb) g_bsum[tid] = sh[tid] - v;
}

__global__ void scan3_kernel() {
    int i = blockIdx.x * 1024 + threadIdx.x;
    if (i < N_NODES) {
        int v = g_off[i] + g_bsum[blockIdx.x];
        g_off[i] = v;
        g_cur[i] = v;
    }
    if (i == 0) g_off[N_NODES] = N_EDGES;
}

__global__ void scatter_kernel() {
    int e = blockIdx.x * 256 + threadIdx.x;
    if (e >= N_EDGES) return;
    int d = g_dst[e];
    int pos = atomicAdd(&g_cur[d], 1);
    g_ssrc[pos] = g_src[e];
}

// ---------------------------------------------------------------------------
// CSR aggregation (warp per node) + fused row-absmax.
// ---------------------------------------------------------------------------
template <int D>
__global__ void agg_csr_kernel(const float* __restrict__ x,
                               float* __restrict__ agg,
                               float* __restrict__ smax) {
    const int node = blockIdx.x * 8 + (threadIdx.x >> 5);
    if (node >= N_NODES) return;
    const int lane = threadIdx.x & 31;
    constexpr int C = D / 4;
    constexpr int R = C / 32;
    const float4* x4 = reinterpret_cast<const float4*>(x);

    float4 acc[R];
#pragma unroll
    for (int j = 0; j < R; j++)
        acc[j] = x4[(size_t)node * C + j * 32 + lane];

    const int e0 = g_off[node];
    const int e1 = g_off[node + 1];
    for (int e = e0; e < e1; e++) {
        int s = g_ssrc[e];
#pragma unroll
        for (int j = 0; j < R; j++) {
            float4 v = x4[(size_t)s * C + j * 32 + lane];
            acc[j].x += v.x;
            acc[j].y += v.y;
            acc[j].z += v.z;
            acc[j].w += v.w;
        }
    }
    float4* a4 = reinterpret_cast<float4*>(agg);
    float m = 0.f;
#pragma unroll
    for (int j = 0; j < R; j++) {
        a4[(size_t)node * C + j * 32 + lane] = acc[j];
        m = fmaxf(m, fmaxf(fmaxf(fabsf(acc[j].x), fabsf(acc[j].y)),
                           fmaxf(fabsf(acc[j].z), fabsf(acc[j].w))));
    }
#pragma unroll
    for (int o = 16; o > 0; o >>= 1)
        m = fmaxf(m, __shfl_xor_sync(0xffffffffu, m, o));
    if (lane == 0) smax[node] = fmaxf(m, 1e-20f);
}

// ---------------------------------------------------------------------------
// int8 double-plane IMMA GEMM: C[M,256] = relu(A[M,K] @ W[K,256] + bias)
// CTA 128x128 (grid Mx2), 512 threads (16 warps 4x4), warp tile 32x32, BK=32.
// SMEM/stage: Aq1[128][48B] | Aq2[128][48B] | Bfrag[2 planes][4KB this n-half]
// ---------------------------------------------------------------------------
#define AQ1_OFF 0
#define AQ2_OFF 6144
#define BF_OFF 12288
#define I8_STAGE 20480
#define SMEM_I8 (2 * I8_STAGE)

template <int NC, bool WSMAX>  // NC = K/32
__global__ __launch_bounds__(512, 1)
void gemm_i8(const float* __restrict__ A, const uint32_t* __restrict__ wq,
             const float* __restrict__ sa_arr, const float* __restrict__ sb_arr,
             const float* __restrict__ bias, float* __restrict__ C,
             float* __restrict__ smax_out, int M) {
    extern __shared__ __align__(1024) char smem[];
    __shared__ unsigned rmx[128];
    const uint32_t sb = smem_u32(smem);
    const int K = NC * 32;
    const int t = threadIdx.x;
    const int lane = t & 31;
    const int warp = t >> 5;
    const int warp_m = warp >> 2;
    const int warp_n = warp & 3;
    const int bm = blockIdx.x * 128;
    const int bn = blockIdx.y * 128;

    if (WSMAX && t < 128) rmx[t] = 0u;

    // A fill coords
    const int a_row = t >> 2;
    const int a_q = t & 3;
    const bool rok = (bm + a_row) < M;
    const float* Ag = A + (size_t)(bm + a_row) * K + a_q * 8;
    const float inv127 = rok ? 127.f / ld_sa(sa_arr, bm + a_row) : 0.f;
    const uint32_t a_st = sb + a_row * 48 + a_q * 8;

    // B fill coords: this CTA's n-half = 16 groups, contiguous per plane.
    // source word offset within chunk: plane*2048 + (bn>>3)*64 + rest
    const int b_pl = t >> 8;        // 0..1 (256 threads per plane, 16B each)
    const int b_rest = t & 255;     // 16B units within plane (4KB)

    // ldmatrix A address (stride 48B rows, conflict-free)
    const uint32_t a_lm =
        sb + (warp_m * 32 + (lane & 15)) * 48 + (lane >> 4) * 16;
    // B fragment base: groups RELATIVE to this CTA's half (bug fix R9)
    const uint32_t b_ld = sb + BF_OFF + (warp_n * 4) * 256 + lane * 8;

    int hi[2][4][4], mid[2][4][4];
#pragma unroll
    for (int i = 0; i < 2; i++)
#pragma unroll
        for (int j = 0; j < 4; j++)
#pragma unroll
            for (int k = 0; k < 4; k++) { hi[i][j][k] = 0; mid[i][j][k] = 0; }

    auto fill_B = [&](int c, int stg) {
        const uint32_t* src =
            wq + (size_t)c * 4096 + b_pl * 2048 + (bn >> 3) * 64 + b_rest * 4;
        CP_ASYNC16(sb + stg * I8_STAGE + BF_OFF + b_pl * 4096 + b_rest * 16,
                   (const void*)src);
        CP_COMMIT();
    };
    auto load_A = [&](int c, float4& v0, float4& v1) {
        if (rok) {
            v0 = *reinterpret_cast<const float4*>(Ag + c * 32);
            v1 = *reinterpret_cast<const float4*>(Ag + c * 32 + 4);
        } else {
            v0 = make_float4(0.f, 0.f, 0.f, 0.f);
            v1 = v0;
        }
    };
    auto store_A = [&](int stg, float4 v0, float4 v1) {
        float f[8] = {v0.x, v0.y, v0.z, v0.w, v1.x, v1.y, v1.z, v1.w};
        uint32_t w1[2] = {0, 0}, w2[2] = {0, 0};
#pragma unroll
        for (int j = 0; j < 8; j++) {
            int q1, q2;
            qpair(f[j] * inv127, q1, q2);
            w1[j >> 2] |= (uint32_t)(q1 & 0xff) << (8 * (j & 3));
            w2[j >> 2] |= (uint32_t)(q2 & 0xff) << (8 * (j & 3));
        }
        uint32_t d = a_st + stg * I8_STAGE;
        asm volatile("st.shared.v2.b32 [%0], {%1,%2};" ::"r"(d), "r"(w1[0]),
                     "r"(w1[1]));
        asm volatile("st.shared.v2.b32 [%0], {%1,%2};" ::"r"(d + AQ2_OFF),
                     "r"(w2[0]), "r"(w2[1]));
    };
    auto compute = [&](int stg) {
        uint32_t Aq1[2][4], Aq2[2][4];
#pragma unroll
        for (int mt = 0; mt < 2; mt++) {
            uint32_t ad = a_lm + stg * I8_STAGE + mt * (16 * 48);
            LDSM4(Aq1[mt], ad);
            LDSM4(Aq2[mt], ad + AQ2_OFF);
        }
#pragma unroll
        for (int g = 0; g < 4; g++) {
            uint32_t Bp1[2], Bp2[2];
            uint32_t bd = b_ld + stg * I8_STAGE + g * 256;
            asm volatile("ld.shared.v2.b32 {%0,%1}, [%2];"
                         : "=r"(Bp1[0]), "=r"(Bp1[1]) : "r"(bd));
            asm volatile("ld.shared.v2.b32 {%0,%1}, [%2];"
                         : "=r"(Bp2[0]), "=r"(Bp2[1]) : "r"(bd + 4096));
#pragma unroll
            for (int mt = 0; mt < 2; mt++) {
                IMMA16832(hi[mt][g], Aq1[mt], Bp1);
                IMMA16832(mid[mt][g], Aq1[mt], Bp2);
                IMMA16832(mid[mt][g], Aq2[mt], Bp1);
            }
        }
    };

    // ---- prologue ----
    {
        fill_B(0, 0);
        float4 v0, v1;
        load_A(0, v0, v1);
        store_A(0, v0, v1);
        CP_WAIT0();
        __syncthreads();
    }
    // ---- main loop ----
    for (int c = 0; c < NC; c++) {
        const int s = c & 1;
        const bool nxt = (c + 1 < NC);
        float4 v0, v1;
        if (nxt) {
            fill_B(c + 1, s ^ 1);
            load_A(c + 1, v0, v1);
        }
        compute(s);
        if (nxt) {
            store_A(s ^ 1, v0, v1);
            CP_WAIT0();
            __syncthreads();
        }
    }

    // ---- epilogue: rescale + bias + relu (+ optional row-max) ----
#pragma unroll
    for (int mt = 0; mt < 2; mt++) {
        int lr0 = warp_m * 32 + mt * 16 + (lane >> 2);
        int r0 = bm + lr0;
        float sa0 = (r0 < M) ? ld_sa(sa_arr, r0) : 1.f;
        float sa1 = (r0 + 8 < M) ? ld_sa(sa_arr, r0 + 8) : 1.f;
        float rm0 = 0.f, rm1 = 0.f;
#pragma unroll
        for (int g = 0; g < 4; g++) {
            int col = bn + warp_n * 32 + g * 8 + (lane & 3) * 2;
            float sb0 = sb_arr[col], sb1 = sb_arr[col + 1];
            float b0 = bias[col], b1 = bias[col + 1];
            float f0 = (float)hi[mt][g][0] + (float)mid[mt][g][0] * (1.f / 254.f);
            float f1 = (float)hi[mt][g][1] + (float)mid[mt][g][1] * (1.f / 254.f);
            float f2 = (float)hi[mt][g][2] + (float)mid[mt][g][2] * (1.f / 254.f);
            float f3 = (float)hi[mt][g][3] + (float)mid[mt][g][3] * (1.f / 254.f);
            if (r0 < M) {
                float2 o;
                o.x = fmaxf(f0 * (sa0 * sb0 * (1.f / 16129.f)) + b0, 0.f);
                o.y = fmaxf(f1 * (sa0 * sb1 * (1.f / 16129.f)) + b1, 0.f);
                *reinterpret_cast<float2*>(C + (size_t)r0 * HID + col) = o;
                rm0 = fmaxf(rm0, fmaxf(o.x, o.y));
            }
            if (r0 + 8 < M) {
                float2 o;
                o.x = fmaxf(f2 * (sa1 * sb0 * (1.f / 16129.f)) + b0, 0.f);
                o.y = fmaxf(f3 * (sa1 * sb1 * (1.f / 16129.f)) + b1, 0.f);
                *reinterpret_cast<float2*>(C + (size_t)(r0 + 8) * HID + col) = o;
                rm1 = fmaxf(rm1, fmaxf(o.x, o.y));
            }
        }
        if (WSMAX) {
            if (r0 < M) atomicMax(&rmx[lr0], __float_as_uint(rm0));
            if (r0 + 8 < M) atomicMax(&rmx[lr0 + 8], __float_as_uint(rm1));
        }
    }
    if (WSMAX) {
        __syncthreads();
        if (t < 128 && bm + t < M)
            atomicMax((unsigned*)&smax_out[bm + t], rmx[t]);
    }
}

// ---------------------------------------------------------------------------
// Final GEMM: out[M,10] = Z[M,256] @ W[256,10] + b. (fp32)
// ---------------------------------------------------------------------------
__global__ void gemm_out_k(const float* __restrict__ Z,
                           const float* __restrict__ W,
                           const float* __restrict__ bias,
                           float* __restrict__ out) {
    __shared__ float Ws[NCLS][HID];
    __shared__ float bs[NCLS];
    const int t = threadIdx.x;
    for (int i = t; i < HID * NCLS; i += 256) {
        int k = i / NCLS;
        int c = i - k * NCLS;
        Ws[c][k] = W[i];
    }
    if (t < NCLS) bs[t] = bias[t];
    __syncthreads();

    const int lane = t & 31;
    const int row = blockIdx.x * 8 + (t >> 5);
    if (row >= N_NODES) return;

    const float* zr = Z + (size_t)row * HID;
    float zv[8];
#pragma unroll
    for (int i = 0; i < 8; i++) zv[i] = zr[i * 32 + lane];

#pragma unroll
    for (int c = 0; c < NCLS; c++) {
        float s = 0.f;
#pragma unroll
        for (int i = 0; i < 8; i++) s += zv[i] * Ws[c][i * 32 + lane];
#pragma unroll
        for (int o = 16; o > 0; o >>= 1) s += __shfl_xor_sync(0xffffffffu, s, o);
        if (lane == 0) out[row * NCLS + c] = s + bs[c];
    }
}

// ---------------------------------------------------------------------------
// Launch sequence (default stream; graph-capturable, alloc-free)
// ---------------------------------------------------------------------------
extern "C" void kernel_launch(void* const* d_in, const int* in_sizes, int n_in,
                              void* d_out, int out_size) {
    (void)in_sizes; (void)n_in; (void)out_size;
    const float* x = (const float*)d_in[0];
    const void* ei = d_in[1];
    const float* W1a = (const float*)d_in[2];
    const float* b1a = (const float*)d_in[3];
    const float* W1b = (const float*)d_in[4];
    const float* b1b = (const float*)d_in[5];
    const float* W2a = (const float*)d_in[6];
    const float* b2a = (const float*)d_in[7];
    const float* W2b = (const float*)d_in[8];
    const float* b2b = (const float*)d_in[9];
    float* out = (float*)d_out;

    float *agg1, *h1, *h, *agg2, *z, *sa1, *sh1, *sa2, *sbv;
    uint32_t *wq1, *wq2, *wq3;
    cudaGetSymbolAddress((void**)&agg1, g_agg1);
    cudaGetSymbolAddress((void**)&h1, g_h1);
    cudaGetSymbolAddress((void**)&h, g_h);
    cudaGetSymbolAddress((void**)&agg2, g_agg2);
    cudaGetSymbolAddress((void**)&z, g_z);
    cudaGetSymbolAddress((void**)&sa1, g_sa1);
    cudaGetSymbolAddress((void**)&sh1, g_sh1);
    cudaGetSymbolAddress((void**)&sa2, g_sa2);
    cudaGetSymbolAddress((void**)&sbv, g_sb);
    cudaGetSymbolAddress((void**)&wq1, g_wq1);
    cudaGetSymbolAddress((void**)&wq2, g_wq2);
    cudaGetSymbolAddress((void**)&wq3, g_wq3);

    cudaFuncSetAttribute(gemm_i8<4, true>,
                         cudaFuncAttributeMaxDynamicSharedMemorySize, SMEM_I8);
    cudaFuncSetAttribute(gemm_i8<8, false>,
                         cudaFuncAttributeMaxDynamicSharedMemorySize, SMEM_I8);

    // ---- setup + CSR build ----
    const int scan_blocks = (N_NODES + 1023) / 1024;  // 98
    setup_colmax_kernel<<<3 + (N_NODES + 255) / 256, 256>>>(W1a, W1b, W2a);
    setup_quant_kernel<<<(8 * 4096 + 255) / 256, 256>>>(W1a, W1b, W2a);
    convert_hist_kernel<<<(N_EDGES + 255) / 256, 256>>>(ei);
    scan1_kernel<<<scan_blocks, 1024>>>();
    scan2_kernel<<<1, 128>>>(scan_blocks);
    scan3_kernel<<<scan_blocks, 1024>>>();
    scatter_kernel<<<(N_EDGES + 255) / 256, 256>>>();

    const dim3 tg((N_NODES + 127) / 128, 2);
    const int agg_blocks = (N_NODES + 7) / 8;

    // ---- layer 1 ----
    agg_csr_kernel<FEAT><<<agg_blocks, 256>>>(x, agg1, sa1);
    gemm_i8<4, true><<<tg, 512, SMEM_I8>>>(agg1, wq1, sa1, sbv, b1a, h1, sh1,
                                           N_NODES);
    gemm_i8<8, false><<<tg, 512, SMEM_I8>>>(h1, wq2, sh1, sbv + 256, b1b, h,
                                            nullptr, N_NODES);
    // ---- layer 2 ----
    agg_csr_kernel<HID><<<agg_blocks, 256>>>(h, agg2, sa2);
    gemm_i8<8, false><<<tg, 512, SMEM_I8>>>(agg2, wq3, sa2, sbv + 512, b2a, z,
                                            nullptr, N_NODES);
    gemm_out_k<<<(N_NODES + 7) / 8, 256>>>(z, W2b, b2b, out);
}